// round 1
// baseline (speedup 1.0000x reference)
#include <cuda_runtime.h>

// Problem constants (fixed shapes for this problem)
#define Nn 8
#define Cc 256
#define Tt 1024
#define Vv 25
#define Hh 8
#define Dd 64
#define HC 512   // Hh * Dd

// SMEM row paddings (chosen for conflict-free access patterns)
#define FPAD 26   // feature rows
#define VPAD 29   // v rows (odd -> conflict-free strided reads)
#define ZPAD 28   // z rows (multiple of 4 -> float4 aligned)
#define WPAD 65   // weight rows (odd -> conflict-free per-thread row reads)

// Precomputed small tensors (batch/time independent)
__device__ float g_q[HC * Vv];
__device__ float g_k[HC * Vv];
__device__ float g_attn[Hh * Vv * Vv];

// ---------------------------------------------------------------------------
// Kernel 1: q = Wq @ tf + bq, k = Wk @ tf + bk   (tf = text_feature [512,25])
// ---------------------------------------------------------------------------
__global__ void qk_kernel(const float* __restrict__ tf,
                          const float* __restrict__ Wq, const float* __restrict__ bq,
                          const float* __restrict__ Wk, const float* __restrict__ bk) {
    extern __shared__ float tf_s[];  // 512*25 floats
    for (int idx = threadIdx.x; idx < HC * Vv; idx += blockDim.x) tf_s[idx] = tf[idx];
    __syncthreads();

    int gt = blockIdx.x * blockDim.x + threadIdx.x;
    int nthreads = gridDim.x * blockDim.x;
    const int total = 2 * HC * Vv;
    for (int g = gt; g < total; g += nthreads) {
        int which = (g >= HC * Vv) ? 1 : 0;
        int r = which ? (g - HC * Vv) : g;
        int hc = r / Vv;
        int u = r - hc * Vv;
        const float* W = which ? Wk : Wq;
        float acc = which ? bk[hc] : bq[hc];
        const float* wrow = W + hc * 512;
#pragma unroll 8
        for (int i = 0; i < 512; i++) acc += wrow[i] * tf_s[i * Vv + u];
        if (which) g_k[r] = acc; else g_q[r] = acc;
    }
}

// ---------------------------------------------------------------------------
// Kernel 2: energy[h,u,v] = sum_c q[h,c,u]*k[h,c,v] / 8 ; attn = softmax_v
// ---------------------------------------------------------------------------
__global__ void attn_kernel() {
    extern __shared__ float s[];
    float* q_s = s;              // 12800
    float* k_s = s + HC * Vv;    // 12800
    for (int idx = threadIdx.x; idx < HC * Vv; idx += blockDim.x) {
        q_s[idx] = g_q[idx];
        k_s[idx] = g_k[idx];
    }
    __syncthreads();

    int r = threadIdx.x;  // one thread per (h,u)
    if (r < Hh * Vv) {
        int h = r / Vv;
        int u = r - h * Vv;
        float e[Vv];
#pragma unroll
        for (int j = 0; j < Vv; j++) e[j] = 0.f;
        const float* qb = q_s + h * Dd * Vv;
        const float* kb = k_s + h * Dd * Vv;
        for (int c = 0; c < Dd; c++) {
            float qv = qb[c * Vv + u];
#pragma unroll
            for (int j = 0; j < Vv; j++) e[j] += qv * kb[c * Vv + j];
        }
        float m = -1e30f;
#pragma unroll
        for (int j = 0; j < Vv; j++) { e[j] *= 0.125f; m = fmaxf(m, e[j]); }
        float ssum = 0.f;
#pragma unroll
        for (int j = 0; j < Vv; j++) { e[j] = expf(e[j] - m); ssum += e[j]; }
        float inv = 1.f / ssum;
        float* arow = g_attn + (h * Vv + u) * Vv;
#pragma unroll
        for (int j = 0; j < Vv; j++) arow[j] = e[j] * inv;
    }
}

// ---------------------------------------------------------------------------
// Kernel 3 (main): one block per (n,t).
//   v   = Wv @ f_nt + bv                     [64,25]
//   z_h = v @ attn_h (h=0..7)                [512,25]
//   out = Wo @ z + bo + f_nt                 [256,25]
// SMEM: f tile, Wv^T / Wo-chunk (union), v, z, attn.
// ---------------------------------------------------------------------------
__global__ void __launch_bounds__(256, 1)
main_kernel(const float* __restrict__ f, const float* __restrict__ Wv,
            const float* __restrict__ bv, const float* __restrict__ Wo,
            const float* __restrict__ bo, float* __restrict__ out) {
    extern __shared__ float s[];
    float* f_s    = s;                         // 256*26 = 6656 floats
    float* v_s    = f_s + Cc * FPAD;           // 64*29  = 1856
    float* z_s    = v_s + Dd * VPAD;           // 512*28 = 14336 (16B aligned)
    float* attn_s = z_s + HC * ZPAD;           // 5000
    float* w_s    = attn_s + Hh * Vv * Vv;     // 256*65 = 16640 (union: Wv^T then Wo chunks)

    const int tid = threadIdx.x;
    const int b = blockIdx.x;
    const int n = b >> 10;          // Tt = 1024
    const int t = b & (Tt - 1);

    const float* fbase = f + (size_t)n * (Cc * Tt * Vv) + (size_t)t * Vv;

    // --- stage 0: cooperative loads ---
    for (int idx = tid; idx < Cc * Vv; idx += 256) {
        int i = idx / Vv;
        int u = idx - i * Vv;
        f_s[i * FPAD + u] = fbase[(size_t)i * (Tt * Vv) + u];
    }
    // Wv transposed: w_s[i*WPAD + c] = Wv[c,i]  (conflict-free stores & reads)
    for (int idx = tid; idx < Dd * Cc; idx += 256) {
        int c = idx >> 8;
        int i = idx & 255;
        w_s[i * WPAD + c] = Wv[idx];
    }
    for (int idx = tid; idx < Hh * Vv * Vv; idx += 256) attn_s[idx] = g_attn[idx];
    __syncthreads();

    // --- stage 1: v[c,u] = bv[c] + sum_i Wv[c,i] * f[i,u] ---
    {
        int c = tid >> 2;       // 0..63
        int ul = tid & 3;       // u = ul, ul+4, ...
        float acc[7];
#pragma unroll
        for (int j = 0; j < 7; j++) acc[j] = 0.f;
        for (int i = 0; i < Cc; i++) {
            float w = w_s[i * WPAD + c];
#pragma unroll
            for (int j = 0; j < 7; j++) {
                int u = ul + 4 * j;
                if (u < Vv) acc[j] += w * f_s[i * FPAD + u];
            }
        }
        float bb = bv[c];
#pragma unroll
        for (int j = 0; j < 7; j++) {
            int u = ul + 4 * j;
            if (u < Vv) v_s[c * VPAD + u] = acc[j] + bb;
        }
    }
    __syncthreads();

    // --- stage 2: z[h*64+c, vv] = sum_u v[c,u] * attn[h,u,vv] ---
#pragma unroll
    for (int rep = 0; rep < 2; rep++) {
        int hc = tid + rep * 256;
        int h = hc >> 6;
        int cc = hc & 63;
        const float* arow = attn_s + h * (Vv * Vv);
        float acc[Vv];
#pragma unroll
        for (int j = 0; j < Vv; j++) acc[j] = 0.f;
#pragma unroll 5
        for (int u = 0; u < Vv; u++) {
            float vval = v_s[cc * VPAD + u];
#pragma unroll
            for (int j = 0; j < Vv; j++) acc[j] += vval * arow[u * Vv + j];
        }
#pragma unroll
        for (int j = 0; j < Vv; j++) z_s[hc * ZPAD + j] = acc[j];
    }
    __syncthreads();

    // --- stage 3: out[o,u] = sum_hc Wo[o,hc] * z[hc,u], chunked over hc ---
    {
        const int o = tid;
        float acc[Vv];
#pragma unroll
        for (int j = 0; j < Vv; j++) acc[j] = 0.f;

        const float4* Wo4 = (const float4*)Wo;
        for (int kk0 = 0; kk0 < HC; kk0 += 64) {
            __syncthreads();  // previous consumers of w_s done
            // load Wo[:, kk0:kk0+64] -> w_s[oo*WPAD + kk]
            for (int idx4 = tid; idx4 < 256 * 16; idx4 += 256) {
                int oo = idx4 >> 4;
                int kq = idx4 & 15;
                float4 wv = Wo4[oo * 128 + (kk0 >> 2) + kq];
                int base = oo * WPAD + kq * 4;
                w_s[base + 0] = wv.x;
                w_s[base + 1] = wv.y;
                w_s[base + 2] = wv.z;
                w_s[base + 3] = wv.w;
            }
            __syncthreads();

#pragma unroll 4
            for (int kk = 0; kk < 64; kk++) {
                float w = w_s[o * WPAD + kk];
                const float* zr = z_s + (kk0 + kk) * ZPAD;
                const float4* zr4 = (const float4*)zr;
#pragma unroll
                for (int q4 = 0; q4 < 6; q4++) {
                    float4 zv = zr4[q4];
                    acc[q4 * 4 + 0] += w * zv.x;
                    acc[q4 * 4 + 1] += w * zv.y;
                    acc[q4 * 4 + 2] += w * zv.z;
                    acc[q4 * 4 + 3] += w * zv.w;
                }
                acc[24] += w * zr[24];
            }
        }

        // epilogue: + bo + residual feature
        float bb = bo[o];
        float* orow = out + ((size_t)(n * Cc + o) * Tt + t) * Vv;
        const float* frow = f_s + o * FPAD;
#pragma unroll
        for (int j = 0; j < Vv; j++) orow[j] = acc[j] + bb + frow[j];
    }
}

// ---------------------------------------------------------------------------
extern "C" void kernel_launch(void* const* d_in, const int* in_sizes, int n_in,
                              void* d_out, int out_size) {
    const float* feature = (const float*)d_in[0];
    const float* tf      = (const float*)d_in[1];
    const float* Wq      = (const float*)d_in[2];
    const float* bq      = (const float*)d_in[3];
    const float* Wk      = (const float*)d_in[4];
    const float* bk      = (const float*)d_in[5];
    const float* Wv      = (const float*)d_in[6];
    const float* bv      = (const float*)d_in[7];
    const float* Wo      = (const float*)d_in[8];
    const float* bo      = (const float*)d_in[9];
    float* out = (float*)d_out;

    const size_t qk_smem   = (size_t)HC * Vv * sizeof(float);                   // 51200
    const size_t attn_smem = (size_t)2 * HC * Vv * sizeof(float);               // 102400
    const size_t main_smem = (size_t)(Cc * FPAD + Dd * VPAD + HC * ZPAD +
                                      Hh * Vv * Vv + Cc * WPAD) * sizeof(float); // 177952

    cudaFuncSetAttribute((const void*)qk_kernel,
                         cudaFuncAttributeMaxDynamicSharedMemorySize, (int)qk_smem);
    cudaFuncSetAttribute((const void*)attn_kernel,
                         cudaFuncAttributeMaxDynamicSharedMemorySize, (int)attn_smem);
    cudaFuncSetAttribute((const void*)main_kernel,
                         cudaFuncAttributeMaxDynamicSharedMemorySize, (int)main_smem);

    qk_kernel<<<32, 256, qk_smem>>>(tf, Wq, bq, Wk, bk);
    attn_kernel<<<1, 256, attn_smem>>>();
    main_kernel<<<Nn * Tt, 256, main_smem>>>(feature, Wv, bv, Wo, bo, out);
}